// round 1
// baseline (speedup 1.0000x reference)
#include <cuda_runtime.h>

// Soft decision tree path probabilities.
// DEPTH=8, N_NODES=255, N_LEAVES=256, BATCH=512.
//
// path_prob for heap node i = product over ancestors a of:
//   x[b,a]     if path took child 2a+1 ("right" mask)
//   1-x[b,a]   if path took child 2a+2 ("left" mask)
// Leaf j (0..255): parent node 127 + (j>>1), last factor chosen by bit j&1
// (0 -> x, 1 -> 1-x). Leaf DFS order == MSB-first path bits == heap order.
//
// Output: [ leaf_probs (512 x 256) ; node_probs (512 x 255) ] row-major.

__global__ __launch_bounds__(256) void tree_path_kernel(
    const float* __restrict__ x,   // (BATCH, 255)
    float* __restrict__ out,       // 512*256 leaf + 512*255 node
    int batch)
{
    __shared__ float xs[256];      // x row (255 used)
    __shared__ float probs[256];   // heap node probs (255 used)

    const int b = blockIdx.x;
    const int t = threadIdx.x;

    const float* xrow = x + (size_t)b * 255;
    if (t < 255) xs[t] = xrow[t];
    if (t == 0)  probs[0] = 1.0f;
    __syncthreads();

    // Levels 1..7: node at level l, offset t (t < 2^l), heap index (2^l-1)+t.
    // Parent heap index (2^(l-1)-1)+(t>>1). Write range [2^l-1, 2^(l+1)-2]
    // is disjoint from read range, so one barrier per level is enough.
#pragma unroll
    for (int l = 1; l < 8; ++l) {
        const int cnt = 1 << l;
        if (t < cnt) {
            const int pidx = (cnt >> 1) - 1 + (t >> 1);
            const float px = xs[pidx];
            probs[cnt - 1 + t] = probs[pidx] * ((t & 1) ? (1.0f - px) : px);
        }
        __syncthreads();
    }

    // Leaves: 256 of them, parent at heap index 127 + (t>>1).
    {
        const int pidx = 127 + (t >> 1);
        const float px = xs[pidx];
        const float leaf = probs[pidx] * ((t & 1) ? (1.0f - px) : px);
        out[(size_t)b * 256 + t] = leaf;
    }

    // Node probs block starts after all leaf probs.
    float* out_nodes = out + (size_t)batch * 256;
    if (t < 255) {
        out_nodes[(size_t)b * 255 + t] = probs[t];
    }
}

extern "C" void kernel_launch(void* const* d_in, const int* in_sizes, int n_in,
                              void* d_out, int out_size) {
    const float* x = (const float*)d_in[0];  // (BATCH, 255) float32
    float* out = (float*)d_out;
    const int batch = in_sizes[0] / 255;     // 512
    tree_path_kernel<<<batch, 256>>>(x, out, batch);
}